// round 2
// baseline (speedup 1.0000x reference)
#include <cuda_runtime.h>

#define NH 8

// Scratch for per-head unitaries (columns of U): layout [h][col][row]
__device__ float g_Ur[NH * 16 * 16];
__device__ float g_Ui[NH * 16 * 16];

// ---------------------------------------------------------------------------
// Setup: evolve each basis state e_col through the fixed (param) circuit for
// head h. 128 threads = 8 heads x 16 columns. Matches reference gate defs:
//   RX(t) = [[c, -is],[-is, c]], RY(t) = [[c,-s],[s,c]], RZ = diag(e^-it/2, e^it/2)
//   qubit q occupies bit (3-q) of the state index (qubit 0 = MSB).
// ---------------------------------------------------------------------------
__global__ void build_unitaries(const float* __restrict__ params) {
    int tid = threadIdx.x;
    if (tid >= NH * 16) return;
    int h = tid >> 4;
    int col = tid & 15;

    float vr[16], vi[16];
#pragma unroll
    for (int i = 0; i < 16; i++) { vr[i] = 0.f; vi[i] = 0.f; }
    vr[col] = 1.f;

    for (int l = 0; l < 2; l++) {
#pragma unroll
        for (int q = 0; q < 4; q++) {
            const float* ph = params + ((h * 2 + l) * 4 + q) * 3;
            const int mask = 8 >> q;
            float c, s;
            // RX
            sincosf(0.5f * ph[0], &s, &c);
#pragma unroll
            for (int i = 0; i < 16; i++) {
                if (!(i & mask)) {
                    int j = i | mask;
                    float ar0 = vr[i], ai0 = vi[i], ar1 = vr[j], ai1 = vi[j];
                    vr[i] = c * ar0 + s * ai1;
                    vi[i] = c * ai0 - s * ar1;
                    vr[j] = s * ai0 + c * ar1;
                    vi[j] = -s * ar0 + c * ai1;
                }
            }
            // RY
            sincosf(0.5f * ph[1], &s, &c);
#pragma unroll
            for (int i = 0; i < 16; i++) {
                if (!(i & mask)) {
                    int j = i | mask;
                    float ar0 = vr[i], ai0 = vi[i], ar1 = vr[j], ai1 = vi[j];
                    vr[i] = c * ar0 - s * ar1;
                    vi[i] = c * ai0 - s * ai1;
                    vr[j] = s * ar0 + c * ar1;
                    vi[j] = s * ai0 + c * ai1;
                }
            }
            // RZ
            sincosf(0.5f * ph[2], &s, &c);
#pragma unroll
            for (int i = 0; i < 16; i++) {
                if (!(i & mask)) {
                    int j = i | mask;
                    float ar0 = vr[i], ai0 = vi[i], ar1 = vr[j], ai1 = vi[j];
                    vr[i] = c * ar0 + s * ai0;
                    vi[i] = c * ai0 - s * ar0;
                    vr[j] = c * ar1 - s * ai1;
                    vi[j] = c * ai1 + s * ar1;
                }
            }
        }
        // CNOT ring: (0->1), (1->2), (2->3), (3->0). control bit (3-c), target (3-t)
#pragma unroll
        for (int g = 0; g < 4; g++) {
            const int cq = g;
            const int tq = (g + 1) & 3;
            const int cbit = 8 >> cq;
            const int tbit = 8 >> tq;
#pragma unroll
            for (int i = 0; i < 16; i++) {
                if ((i & cbit) && !(i & tbit)) {
                    int j = i | tbit;
                    float tr = vr[i]; vr[i] = vr[j]; vr[j] = tr;
                    float ti = vi[i]; vi[i] = vi[j]; vi[j] = ti;
                }
            }
        }
    }

#pragma unroll
    for (int r = 0; r < 16; r++) {
        g_Ur[(h * 16 + col) * 16 + r] = vr[r];
        g_Ui[(h * 16 + col) * 16 + r] = vi[r];
    }
}

// ---------------------------------------------------------------------------
// Main: one thread per token. s = tensor product of (cos, sin) pairs,
// v = U_h s (2 real matvecs), p = |v|^2, ev via compile-time-signed sums,
// output linear folded into the head loop.
// ---------------------------------------------------------------------------
__global__ __launch_bounds__(256) void qmha_main(
    const float* __restrict__ x,
    const float* __restrict__ W,      // [32][32] row-major (out = ev @ W^T + b)
    const float* __restrict__ bvec,   // [32]
    float* __restrict__ out,
    int ntok)
{
    __shared__ __align__(16) float sUr[NH * 256];
    __shared__ __align__(16) float sUi[NH * 256];
    __shared__ __align__(16) float sWt[32 * 32];  // sWt[k*32+j] = W[j*32+k]
    __shared__ float sb[32];

    for (int i = threadIdx.x; i < NH * 256; i += blockDim.x) {
        sUr[i] = g_Ur[i];
        sUi[i] = g_Ui[i];
    }
    for (int i = threadIdx.x; i < 1024; i += blockDim.x) {
        int k = i >> 5, j = i & 31;
        sWt[k * 32 + j] = W[j * 32 + k];
    }
    if (threadIdx.x < 32) sb[threadIdx.x] = bvec[threadIdx.x];
    __syncthreads();

    int t = blockIdx.x * blockDim.x + threadIdx.x;
    if (t >= ntok) return;

    const float4* xt = reinterpret_cast<const float4*>(x + (size_t)t * 32);

    float acc[32];
#pragma unroll
    for (int j = 0; j < 32; j++) acc[j] = sb[j];

#pragma unroll
    for (int h = 0; h < NH; h++) {
        float4 ang = xt[h];
        float c0, s0, c1, s1, c2, s2, c3, s3;
        __sincosf(0.5f * ang.x, &s0, &c0);
        __sincosf(0.5f * ang.y, &s1, &c1);
        __sincosf(0.5f * ang.z, &s2, &c2);
        __sincosf(0.5f * ang.w, &s3, &c3);

        float ab[4] = { c0 * c1, c0 * s1, s0 * c1, s0 * s1 };
        float cd[4] = { c2 * c3, c2 * s3, s2 * c3, s2 * s3 };
        float sv[16];
#pragma unroll
        for (int i = 0; i < 4; i++)
#pragma unroll
            for (int j = 0; j < 4; j++)
                sv[i * 4 + j] = ab[i] * cd[j];

        float vr[16], vi[16];
#pragma unroll
        for (int i = 0; i < 16; i++) { vr[i] = 0.f; vi[i] = 0.f; }

        const float4* Ur4 = reinterpret_cast<const float4*>(sUr + h * 256);
        const float4* Ui4 = reinterpret_cast<const float4*>(sUi + h * 256);
#pragma unroll
        for (int col = 0; col < 16; col++) {
            float sc = sv[col];
#pragma unroll
            for (int rq = 0; rq < 4; rq++) {
                float4 u = Ur4[col * 4 + rq];
                vr[rq * 4 + 0] += u.x * sc;
                vr[rq * 4 + 1] += u.y * sc;
                vr[rq * 4 + 2] += u.z * sc;
                vr[rq * 4 + 3] += u.w * sc;
                float4 w = Ui4[col * 4 + rq];
                vi[rq * 4 + 0] += w.x * sc;
                vi[rq * 4 + 1] += w.y * sc;
                vi[rq * 4 + 2] += w.z * sc;
                vi[rq * 4 + 3] += w.w * sc;
            }
        }

        float e0 = 0.f, e1 = 0.f, e2 = 0.f, e3 = 0.f;
#pragma unroll
        for (int k = 0; k < 16; k++) {
            float p = vr[k] * vr[k] + vi[k] * vi[k];
            e0 += (k & 8) ? -p : p;
            e1 += (k & 4) ? -p : p;
            e2 += (k & 2) ? -p : p;
            e3 += (k & 1) ? -p : p;
        }

        float ev[4] = { e0, e1, e2, e3 };
#pragma unroll
        for (int i = 0; i < 4; i++) {
            float e = ev[i];
            const float4* w4 = reinterpret_cast<const float4*>(sWt + (h * 4 + i) * 32);
#pragma unroll
            for (int j4 = 0; j4 < 8; j4++) {
                float4 w = w4[j4];
                acc[j4 * 4 + 0] += e * w.x;
                acc[j4 * 4 + 1] += e * w.y;
                acc[j4 * 4 + 2] += e * w.z;
                acc[j4 * 4 + 3] += e * w.w;
            }
        }
    }

    float4* o = reinterpret_cast<float4*>(out + (size_t)t * 32);
#pragma unroll
    for (int j4 = 0; j4 < 8; j4++)
        o[j4] = make_float4(acc[j4 * 4 + 0], acc[j4 * 4 + 1],
                            acc[j4 * 4 + 2], acc[j4 * 4 + 3]);
}

extern "C" void kernel_launch(void* const* d_in, const int* in_sizes, int n_in,
                              void* d_out, int out_size) {
    const float* x      = (const float*)d_in[0];  // [B,S,32]
    const float* params = (const float*)d_in[1];  // [8,2,4,3]
    const float* W      = (const float*)d_in[2];  // [32,32]
    const float* b      = (const float*)d_in[3];  // [32]
    float* out = (float*)d_out;

    int ntok = in_sizes[0] / 32;

    build_unitaries<<<1, 128>>>(params);
    int blocks = (ntok + 255) / 256;
    qmha_main<<<blocks, 256>>>(x, W, b, out, ntok);
}

// round 3
// speedup vs baseline: 1.0196x; 1.0196x over previous
#include <cuda_runtime.h>

#define NH 8

// Per-head unitaries (columns of U): layout [h][col][row]
__device__ float g_Ur[NH * 16 * 16];
__device__ float g_Ui[NH * 16 * 16];
// Per-head bilinear coefficient tensor: g_C[h*81 + p*9 + q] = (C0,C1,C2,C3)
// where ev_i = sum_{p,q} g01[p] * C_i[p][q] * g23[q]
__device__ float4 g_C[NH * 81];

// ---------------------------------------------------------------------------
// Setup 1: evolve basis states through the fixed param circuit (unchanged,
// verified correct in round 1). 128 threads = 8 heads x 16 columns.
// ---------------------------------------------------------------------------
__global__ void build_unitaries(const float* __restrict__ params) {
    int tid = threadIdx.x;
    if (tid >= NH * 16) return;
    int h = tid >> 4;
    int col = tid & 15;

    float vr[16], vi[16];
#pragma unroll
    for (int i = 0; i < 16; i++) { vr[i] = 0.f; vi[i] = 0.f; }
    vr[col] = 1.f;

    for (int l = 0; l < 2; l++) {
#pragma unroll
        for (int q = 0; q < 4; q++) {
            const float* ph = params + ((h * 2 + l) * 4 + q) * 3;
            const int mask = 8 >> q;
            float c, s;
            // RX
            sincosf(0.5f * ph[0], &s, &c);
#pragma unroll
            for (int i = 0; i < 16; i++) {
                if (!(i & mask)) {
                    int j = i | mask;
                    float ar0 = vr[i], ai0 = vi[i], ar1 = vr[j], ai1 = vi[j];
                    vr[i] = c * ar0 + s * ai1;
                    vi[i] = c * ai0 - s * ar1;
                    vr[j] = s * ai0 + c * ar1;
                    vi[j] = -s * ar0 + c * ai1;
                }
            }
            // RY
            sincosf(0.5f * ph[1], &s, &c);
#pragma unroll
            for (int i = 0; i < 16; i++) {
                if (!(i & mask)) {
                    int j = i | mask;
                    float ar0 = vr[i], ai0 = vi[i], ar1 = vr[j], ai1 = vi[j];
                    vr[i] = c * ar0 - s * ar1;
                    vi[i] = c * ai0 - s * ai1;
                    vr[j] = s * ar0 + c * ar1;
                    vi[j] = s * ai0 + c * ai1;
                }
            }
            // RZ
            sincosf(0.5f * ph[2], &s, &c);
#pragma unroll
            for (int i = 0; i < 16; i++) {
                if (!(i & mask)) {
                    int j = i | mask;
                    float ar0 = vr[i], ai0 = vi[i], ar1 = vr[j], ai1 = vi[j];
                    vr[i] = c * ar0 + s * ai0;
                    vi[i] = c * ai0 - s * ar0;
                    vr[j] = c * ar1 - s * ai1;
                    vi[j] = c * ai1 + s * ar1;
                }
            }
        }
        // CNOT ring
#pragma unroll
        for (int g = 0; g < 4; g++) {
            const int cbit = 8 >> g;
            const int tbit = 8 >> ((g + 1) & 3);
#pragma unroll
            for (int i = 0; i < 16; i++) {
                if ((i & cbit) && !(i & tbit)) {
                    int j = i | tbit;
                    float tr = vr[i]; vr[i] = vr[j]; vr[j] = tr;
                    float ti = vi[i]; vi[i] = vi[j]; vi[j] = ti;
                }
            }
        }
    }

#pragma unroll
    for (int r = 0; r < 16; r++) {
        g_Ur[(h * 16 + col) * 16 + r] = vr[r];
        g_Ui[(h * 16 + col) * 16 + r] = vi[r];
    }
}

// ---------------------------------------------------------------------------
// Setup 2: build the 9x9x4 coefficient tensor per head.
//   M_i[j][k] = sum_r z_i(r) (Ur[r,j]Ur[r,k] + Ui[r,j]Ui[r,k])   (real symmetric)
//   C_i[m0..m3] = (1/16) * sum over 16 sparse branch combos of +/- M_i[j][k]
// with per-qubit basis {1, cos, sin}:
//   m=0: (j,k)=(b,b), sgn +      (from c^2=(1+c)/2, s^2=(1-c)/2 summed)
//   m=1: (j,k)=(b,b), sgn (-1)^b
//   m=2: (j,k)=(b,1-b), sgn +    (from cs = s/2)
// One block per head.
// ---------------------------------------------------------------------------
__global__ void build_coeffs() {
    int h = blockIdx.x;
    int tid = threadIdx.x;  // 128 threads
    __shared__ float sM[4][16][16];

    for (int e = tid; e < 4 * 256; e += 128) {
        int i = e >> 8;
        int j = (e >> 4) & 15;
        int k = e & 15;
        int zmask = 8 >> i;
        const float* urj = &g_Ur[(h * 16 + j) * 16];
        const float* urk = &g_Ur[(h * 16 + k) * 16];
        const float* uij = &g_Ui[(h * 16 + j) * 16];
        const float* uik = &g_Ui[(h * 16 + k) * 16];
        float acc = 0.f;
#pragma unroll
        for (int r = 0; r < 16; r++) {
            float t = urj[r] * urk[r] + uij[r] * uik[r];
            acc += (r & zmask) ? -t : t;
        }
        sM[i][j][k] = acc;
    }
    __syncthreads();

    for (int m = tid; m < 81; m += 128) {
        int p = m / 9, q = m % 9;
        int mq[4] = { p / 3, p % 3, q / 3, q % 3 };
        float c0 = 0.f, c1 = 0.f, c2 = 0.f, c3 = 0.f;
        for (int t = 0; t < 16; t++) {
            int j = 0, k = 0;
            float sgn = 1.f;
#pragma unroll
            for (int qq = 0; qq < 4; qq++) {
                int b = (t >> (3 - qq)) & 1;
                int jq, kq;
                if (mq[qq] == 0)      { jq = b; kq = b; }
                else if (mq[qq] == 1) { jq = b; kq = b; if (b) sgn = -sgn; }
                else                  { jq = b; kq = 1 - b; }
                j = (j << 1) | jq;
                k = (k << 1) | kq;
            }
            c0 += sgn * sM[0][j][k];
            c1 += sgn * sM[1][j][k];
            c2 += sgn * sM[2][j][k];
            c3 += sgn * sM[3][j][k];
        }
        g_C[h * 81 + m] = make_float4(c0 * 0.0625f, c1 * 0.0625f,
                                      c2 * 0.0625f, c3 * 0.0625f);
    }
}

// ---------------------------------------------------------------------------
// Main: 2 tokens per thread (shares all shared-memory loads of C and W).
// Per head: g01,g23 trig features (full angle), ev = bilinear form, fold W.
// ---------------------------------------------------------------------------
__global__ __launch_bounds__(128, 3) void qmha_main(
    const float* __restrict__ x,
    const float* __restrict__ W,      // [32][32] row-major (out = ev @ W^T + b)
    const float* __restrict__ bvec,   // [32]
    float* __restrict__ out,
    int ntok)
{
    __shared__ __align__(16) float4 sC[NH * 81];
    __shared__ __align__(16) float sWt[32 * 32];  // sWt[k*32+j] = W[j*32+k]
    __shared__ float sb[32];

    for (int i = threadIdx.x; i < NH * 81; i += 128) sC[i] = g_C[i];
    for (int i = threadIdx.x; i < 1024; i += 128) {
        int k = i >> 5, j = i & 31;
        sWt[k * 32 + j] = W[j * 32 + k];
    }
    if (threadIdx.x < 32) sb[threadIdx.x] = bvec[threadIdx.x];
    __syncthreads();

    int half = (ntok + 1) >> 1;
    int t0 = blockIdx.x * 128 + threadIdx.x;
    if (t0 >= half) return;
    int t1 = t0 + half;
    bool has1 = (t1 < ntok);

    const float4* xA = reinterpret_cast<const float4*>(x + (size_t)t0 * 32);
    const float4* xB = reinterpret_cast<const float4*>(x + (size_t)(has1 ? t1 : t0) * 32);

    float accA[32], accB[32];
#pragma unroll
    for (int j = 0; j < 32; j++) { accA[j] = sb[j]; accB[j] = sb[j]; }

#pragma unroll
    for (int h = 0; h < NH; h++) {
        float4 aA = xA[h];
        float4 aB = xB[h];
        float cA0, sA0, cA1, sA1, cA2, sA2, cA3, sA3;
        float cB0, sB0, cB1, sB1, cB2, sB2, cB3, sB3;
        __sincosf(aA.x, &sA0, &cA0);
        __sincosf(aA.y, &sA1, &cA1);
        __sincosf(aA.z, &sA2, &cA2);
        __sincosf(aA.w, &sA3, &cA3);
        __sincosf(aB.x, &sB0, &cB0);
        __sincosf(aB.y, &sB1, &cB1);
        __sincosf(aB.z, &sB2, &cB2);
        __sincosf(aB.w, &sB3, &cB3);

        float g01A[9] = { 1.f, cA1, sA1, cA0, cA0*cA1, cA0*sA1, sA0, sA0*cA1, sA0*sA1 };
        float g23A[9] = { 1.f, cA3, sA3, cA2, cA2*cA3, cA2*sA3, sA2, sA2*cA3, sA2*sA3 };
        float g01B[9] = { 1.f, cB1, sB1, cB0, cB0*cB1, cB0*sB1, sB0, sB0*cB1, sB0*sB1 };
        float g23B[9] = { 1.f, cB3, sB3, cB2, cB2*cB3, cB2*sB3, sB2, sB2*cB3, sB2*sB3 };

        float4 evA = make_float4(0.f, 0.f, 0.f, 0.f);
        float4 evB = make_float4(0.f, 0.f, 0.f, 0.f);
        const float4* C = &sC[h * 81];
#pragma unroll
        for (int p = 0; p < 9; p++) {
            float4 tA = make_float4(0.f, 0.f, 0.f, 0.f);
            float4 tB = make_float4(0.f, 0.f, 0.f, 0.f);
#pragma unroll
            for (int q = 0; q < 9; q++) {
                float4 c4 = C[p * 9 + q];
                float gA = g23A[q], gB = g23B[q];
                tA.x += c4.x * gA; tA.y += c4.y * gA;
                tA.z += c4.z * gA; tA.w += c4.w * gA;
                tB.x += c4.x * gB; tB.y += c4.y * gB;
                tB.z += c4.z * gB; tB.w += c4.w * gB;
            }
            float pA = g01A[p], pB = g01B[p];
            evA.x += pA * tA.x; evA.y += pA * tA.y;
            evA.z += pA * tA.z; evA.w += pA * tA.w;
            evB.x += pB * tB.x; evB.y += pB * tB.y;
            evB.z += pB * tB.z; evB.w += pB * tB.w;
        }

        float evAa[4] = { evA.x, evA.y, evA.z, evA.w };
        float evBa[4] = { evB.x, evB.y, evB.z, evB.w };
#pragma unroll
        for (int i = 0; i < 4; i++) {
            float eA = evAa[i], eB = evBa[i];
            const float4* w4 = reinterpret_cast<const float4*>(sWt + (h * 4 + i) * 32);
#pragma unroll
            for (int j4 = 0; j4 < 8; j4++) {
                float4 w = w4[j4];
                accA[j4 * 4 + 0] += eA * w.x;
                accA[j4 * 4 + 1] += eA * w.y;
                accA[j4 * 4 + 2] += eA * w.z;
                accA[j4 * 4 + 3] += eA * w.w;
                accB[j4 * 4 + 0] += eB * w.x;
                accB[j4 * 4 + 1] += eB * w.y;
                accB[j4 * 4 + 2] += eB * w.z;
                accB[j4 * 4 + 3] += eB * w.w;
            }
        }
    }

    float4* oA = reinterpret_cast<float4*>(out + (size_t)t0 * 32);
#pragma unroll
    for (int j4 = 0; j4 < 8; j4++)
        oA[j4] = make_float4(accA[j4 * 4 + 0], accA[j4 * 4 + 1],
                             accA[j4 * 4 + 2], accA[j4 * 4 + 3]);
    if (has1) {
        float4* oB = reinterpret_cast<float4*>(out + (size_t)t1 * 32);
#pragma unroll
        for (int j4 = 0; j4 < 8; j4++)
            oB[j4] = make_float4(accB[j4 * 4 + 0], accB[j4 * 4 + 1],
                                 accB[j4 * 4 + 2], accB[j4 * 4 + 3]);
    }
}

extern "C" void kernel_launch(void* const* d_in, const int* in_sizes, int n_in,
                              void* d_out, int out_size) {
    const float* x      = (const float*)d_in[0];  // [B,S,32]
    const float* params = (const float*)d_in[1];  // [8,2,4,3]
    const float* W      = (const float*)d_in[2];  // [32,32]
    const float* b      = (const float*)d_in[3];  // [32]
    float* out = (float*)d_out;

    int ntok = in_sizes[0] / 32;
    int half = (ntok + 1) >> 1;

    build_unitaries<<<1, 128>>>(params);
    build_coeffs<<<NH, 128>>>();
    int blocks = (half + 127) / 128;
    qmha_main<<<blocks, 128>>>(x, W, b, out, ntok);
}

// round 5
// speedup vs baseline: 1.4085x; 1.3814x over previous
#include <cuda_runtime.h>

#define NH 8

// Per-head bilinear coefficient tensor: g_C[h*81 + p*9 + q] = (C0,C1,C2,C3)
// where ev_i = sum_{p,q} g01[p] * C_i[p][q] * g23[q]
__device__ float4 g_C[NH * 81];

// ---------------- packed f32x2 helpers ----------------
__device__ __forceinline__ unsigned long long pk2(float lo, float hi) {
    unsigned long long r;
    asm("mov.b64 %0, {%1, %2};" : "=l"(r) : "f"(lo), "f"(hi));
    return r;
}
__device__ __forceinline__ void fma2(unsigned long long& d,
                                     unsigned long long a,
                                     unsigned long long b) {
    asm("fma.rn.f32x2 %0, %1, %2, %0;" : "+l"(d) : "l"(a), "l"(b));
}
__device__ __forceinline__ void unpk2(float& lo, float& hi, unsigned long long v) {
    asm("mov.b64 {%0, %1}, %2;" : "=f"(lo), "=f"(hi) : "l"(v));
}

// ---------------------------------------------------------------------------
// Fused setup: one block per head.
//  Phase A (threads 0-15): evolve basis columns of U through the fixed circuit.
//  Phase B: M_i[j][k] = sum_r z_i(r)(Ur[r,j]Ur[r,k] + Ui[r,j]Ui[r,k])
//  Phase C: contract to the 9x9x4 trig-basis coefficient tensor C.
// ---------------------------------------------------------------------------
__global__ void build_all(const float* __restrict__ params) {
    int h = blockIdx.x;
    int tid = threadIdx.x;
    __shared__ float sUr[16][16];   // [col][row]
    __shared__ float sUi[16][16];
    __shared__ float sM[4][16][16];

    if (tid < 16) {
        int col = tid;
        float vr[16], vi[16];
#pragma unroll
        for (int i = 0; i < 16; i++) { vr[i] = 0.f; vi[i] = 0.f; }
        vr[col] = 1.f;

        for (int l = 0; l < 2; l++) {
#pragma unroll
            for (int q = 0; q < 4; q++) {
                const float* ph = params + ((h * 2 + l) * 4 + q) * 3;
                const int mask = 8 >> q;
                float c, s;
                // RX
                __sincosf(0.5f * ph[0], &s, &c);
#pragma unroll
                for (int i = 0; i < 16; i++) {
                    if (!(i & mask)) {
                        int j = i | mask;
                        float ar0 = vr[i], ai0 = vi[i], ar1 = vr[j], ai1 = vi[j];
                        vr[i] = c * ar0 + s * ai1;
                        vi[i] = c * ai0 - s * ar1;
                        vr[j] = s * ai0 + c * ar1;
                        vi[j] = -s * ar0 + c * ai1;
                    }
                }
                // RY
                __sincosf(0.5f * ph[1], &s, &c);
#pragma unroll
                for (int i = 0; i < 16; i++) {
                    if (!(i & mask)) {
                        int j = i | mask;
                        float ar0 = vr[i], ai0 = vi[i], ar1 = vr[j], ai1 = vi[j];
                        vr[i] = c * ar0 - s * ar1;
                        vi[i] = c * ai0 - s * ai1;
                        vr[j] = s * ar0 + c * ar1;
                        vi[j] = s * ai0 + c * ai1;
                    }
                }
                // RZ
                __sincosf(0.5f * ph[2], &s, &c);
#pragma unroll
                for (int i = 0; i < 16; i++) {
                    if (!(i & mask)) {
                        int j = i | mask;
                        float ar0 = vr[i], ai0 = vi[i], ar1 = vr[j], ai1 = vi[j];
                        vr[i] = c * ar0 + s * ai0;
                        vi[i] = c * ai0 - s * ar0;
                        vr[j] = c * ar1 - s * ai1;
                        vi[j] = c * ai1 + s * ar1;
                    }
                }
            }
            // CNOT ring
#pragma unroll
            for (int g = 0; g < 4; g++) {
                const int cbit = 8 >> g;
                const int tbit = 8 >> ((g + 1) & 3);
#pragma unroll
                for (int i = 0; i < 16; i++) {
                    if ((i & cbit) && !(i & tbit)) {
                        int j = i | tbit;
                        float tr = vr[i]; vr[i] = vr[j]; vr[j] = tr;
                        float ti = vi[i]; vi[i] = vi[j]; vi[j] = ti;
                    }
                }
            }
        }
#pragma unroll
        for (int r = 0; r < 16; r++) {
            sUr[col][r] = vr[r];
            sUi[col][r] = vi[r];
        }
    }
    __syncthreads();

    for (int e = tid; e < 4 * 256; e += blockDim.x) {
        int i = e >> 8;
        int j = (e >> 4) & 15;
        int k = e & 15;
        int zmask = 8 >> i;
        float acc = 0.f;
#pragma unroll
        for (int r = 0; r < 16; r++) {
            float t = sUr[j][r] * sUr[k][r] + sUi[j][r] * sUi[k][r];
            acc += (r & zmask) ? -t : t;
        }
        sM[i][j][k] = acc;
    }
    __syncthreads();

    for (int m = tid; m < 81; m += blockDim.x) {
        int p = m / 9, q = m % 9;
        int mq[4] = { p / 3, p % 3, q / 3, q % 3 };
        float c0 = 0.f, c1 = 0.f, c2 = 0.f, c3 = 0.f;
        for (int t = 0; t < 16; t++) {
            int j = 0, k = 0;
            float sgn = 1.f;
#pragma unroll
            for (int qq = 0; qq < 4; qq++) {
                int b = (t >> (3 - qq)) & 1;
                int jq, kq;
                if (mq[qq] == 0)      { jq = b; kq = b; }
                else if (mq[qq] == 1) { jq = b; kq = b; if (b) sgn = -sgn; }
                else                  { jq = b; kq = 1 - b; }
                j = (j << 1) | jq;
                k = (k << 1) | kq;
            }
            c0 += sgn * sM[0][j][k];
            c1 += sgn * sM[1][j][k];
            c2 += sgn * sM[2][j][k];
            c3 += sgn * sM[3][j][k];
        }
        g_C[h * 81 + m] = make_float4(c0 * 0.0625f, c1 * 0.0625f,
                                      c2 * 0.0625f, c3 * 0.0625f);
    }
}

// ---------------------------------------------------------------------------
// Main: 1 token per thread, packed fma.rn.f32x2 throughout.
//  - bilinear: pack (C0,C1) and (C2,C3) pairs straight from the float4 layout
//  - W-fold:   pack adjacent output pairs (j, j+1)
// ---------------------------------------------------------------------------
__global__ __launch_bounds__(128, 4) void qmha_main(
    const float* __restrict__ x,
    const float* __restrict__ W,      // [32][32] row-major (out = ev @ W^T + b)
    const float* __restrict__ bvec,   // [32]
    float* __restrict__ out,
    int ntok)
{
    __shared__ __align__(16) float4 sC[NH * 81];
    __shared__ __align__(16) float sWt[32 * 32];  // sWt[k*32+j] = W[j*32+k]
    __shared__ float sb[32];

    for (int i = threadIdx.x; i < NH * 81; i += 128) sC[i] = g_C[i];
    for (int i = threadIdx.x; i < 1024; i += 128) {
        int k = i >> 5, j = i & 31;
        sWt[k * 32 + j] = W[j * 32 + k];
    }
    if (threadIdx.x < 32) sb[threadIdx.x] = bvec[threadIdx.x];
    __syncthreads();

    int t = blockIdx.x * 128 + threadIdx.x;
    if (t >= ntok) return;

    const float4* xt = reinterpret_cast<const float4*>(x + (size_t)t * 32);

    unsigned long long acc2[16];   // packed output pairs (2m, 2m+1)
#pragma unroll
    for (int m = 0; m < 16; m++) acc2[m] = pk2(sb[2 * m], sb[2 * m + 1]);

#pragma unroll
    for (int h = 0; h < NH; h++) {
        float4 ang = xt[h];
        float c0, s0, c1, s1, c2, s2, c3, s3;
        __sincosf(ang.x, &s0, &c0);
        __sincosf(ang.y, &s1, &c1);
        __sincosf(ang.z, &s2, &c2);
        __sincosf(ang.w, &s3, &c3);

        float g01[9] = { 1.f, c1, s1, c0, c0*c1, c0*s1, s0, s0*c1, s0*s1 };
        // g23 duplicated into packed lanes once; reused across all 9 p-rows
        unsigned long long g23d[9];
        {
            float g23[9] = { 1.f, c3, s3, c2, c2*c3, c2*s3, s2, s2*c3, s2*s3 };
#pragma unroll
            for (int q = 0; q < 9; q++) g23d[q] = pk2(g23[q], g23[q]);
        }

        unsigned long long ev01 = 0ULL, ev23 = 0ULL;   // packed (e0,e1),(e2,e3)
        const ulonglong2* Cp = reinterpret_cast<const ulonglong2*>(&sC[h * 81]);
#pragma unroll
        for (int p = 0; p < 9; p++) {
            unsigned long long t01 = 0ULL, t23 = 0ULL;
#pragma unroll
            for (int q = 0; q < 9; q++) {
                ulonglong2 cc = Cp[p * 9 + q];       // .x=(C0,C1) .y=(C2,C3)
                fma2(t01, cc.x, g23d[q]);
                fma2(t23, cc.y, g23d[q]);
            }
            unsigned long long gp = pk2(g01[p], g01[p]);
            fma2(ev01, gp, t01);
            fma2(ev23, gp, t23);
        }

        float e0, e1, e2, e3;
        unpk2(e0, e1, ev01);
        unpk2(e2, e3, ev23);
        float ev[4] = { e0, e1, e2, e3 };

#pragma unroll
        for (int i = 0; i < 4; i++) {
            unsigned long long ed = pk2(ev[i], ev[i]);
            const ulonglong2* w2 =
                reinterpret_cast<const ulonglong2*>(sWt + (h * 4 + i) * 32);
#pragma unroll
            for (int r = 0; r < 8; r++) {
                ulonglong2 ww = w2[r];               // 4 floats = 2 packed pairs
                fma2(acc2[2 * r + 0], ed, ww.x);
                fma2(acc2[2 * r + 1], ed, ww.y);
            }
        }
    }

    float4* o = reinterpret_cast<float4*>(out + (size_t)t * 32);
#pragma unroll
    for (int j4 = 0; j4 < 8; j4++) {
        float a, b, c, d;
        unpk2(a, b, acc2[2 * j4 + 0]);
        unpk2(c, d, acc2[2 * j4 + 1]);
        o[j4] = make_float4(a, b, c, d);
    }
}

extern "C" void kernel_launch(void* const* d_in, const int* in_sizes, int n_in,
                              void* d_out, int out_size) {
    const float* x      = (const float*)d_in[0];  // [B,S,32]
    const float* params = (const float*)d_in[1];  // [8,2,4,3]
    const float* W      = (const float*)d_in[2];  // [32,32]
    const float* b      = (const float*)d_in[3];  // [32]
    float* out = (float*)d_out;

    int ntok = in_sizes[0] / 32;

    build_all<<<NH, 128>>>(params);
    int blocks = (ntok + 127) / 128;
    qmha_main<<<blocks, 128>>>(x, W, b, out, ntok);
}

// round 7
// speedup vs baseline: 1.8716x; 1.3288x over previous
#include <cuda_runtime.h>

#define NH 8

// Per-head bilinear coefficient tensor (built on device, then copied to constant):
// g_C[h*81 + p*9 + q] = (C0,C1,C2,C3), ev_i = sum_{p,q} g01[p] * C_i[p][q] * g23[q]
__device__ float4 g_C[NH * 81];
__constant__ ulonglong2 c_C[NH * 81];   // .x=(C0,C1) packed, .y=(C2,C3) packed

// ---------------- packed f32x2 helpers ----------------
__device__ __forceinline__ unsigned long long pk2(float lo, float hi) {
    unsigned long long r;
    asm("mov.b64 %0, {%1, %2};" : "=l"(r) : "f"(lo), "f"(hi));
    return r;
}
__device__ __forceinline__ void fma2(unsigned long long& d,
                                     unsigned long long a,
                                     unsigned long long b) {
    asm("fma.rn.f32x2 %0, %1, %2, %0;" : "+l"(d) : "l"(a), "l"(b));
}
__device__ __forceinline__ void unpk2(float& lo, float& hi, unsigned long long v) {
    asm("mov.b64 {%0, %1}, %2;" : "=f"(lo), "=f"(hi) : "l"(v));
}

// ---------------------------------------------------------------------------
// Fused setup (one block per head): evolve U columns, build M_i, contract to C.
// ---------------------------------------------------------------------------
__global__ void build_all(const float* __restrict__ params) {
    int h = blockIdx.x;
    int tid = threadIdx.x;
    __shared__ float sUr[16][16];   // [col][row]
    __shared__ float sUi[16][16];
    __shared__ float sM[4][16][16];

    if (tid < 16) {
        int col = tid;
        float vr[16], vi[16];
#pragma unroll
        for (int i = 0; i < 16; i++) { vr[i] = 0.f; vi[i] = 0.f; }
        vr[col] = 1.f;

        for (int l = 0; l < 2; l++) {
#pragma unroll
            for (int q = 0; q < 4; q++) {
                const float* ph = params + ((h * 2 + l) * 4 + q) * 3;
                const int mask = 8 >> q;
                float c, s;
                __sincosf(0.5f * ph[0], &s, &c);   // RX
#pragma unroll
                for (int i = 0; i < 16; i++) {
                    if (!(i & mask)) {
                        int j = i | mask;
                        float ar0 = vr[i], ai0 = vi[i], ar1 = vr[j], ai1 = vi[j];
                        vr[i] = c * ar0 + s * ai1;
                        vi[i] = c * ai0 - s * ar1;
                        vr[j] = s * ai0 + c * ar1;
                        vi[j] = -s * ar0 + c * ai1;
                    }
                }
                __sincosf(0.5f * ph[1], &s, &c);   // RY
#pragma unroll
                for (int i = 0; i < 16; i++) {
                    if (!(i & mask)) {
                        int j = i | mask;
                        float ar0 = vr[i], ai0 = vi[i], ar1 = vr[j], ai1 = vi[j];
                        vr[i] = c * ar0 - s * ar1;
                        vi[i] = c * ai0 - s * ai1;
                        vr[j] = s * ar0 + c * ar1;
                        vi[j] = s * ai0 + c * ai1;
                    }
                }
                __sincosf(0.5f * ph[2], &s, &c);   // RZ
#pragma unroll
                for (int i = 0; i < 16; i++) {
                    if (!(i & mask)) {
                        int j = i | mask;
                        float ar0 = vr[i], ai0 = vi[i], ar1 = vr[j], ai1 = vi[j];
                        vr[i] = c * ar0 + s * ai0;
                        vi[i] = c * ai0 - s * ar0;
                        vr[j] = c * ar1 - s * ai1;
                        vi[j] = c * ai1 + s * ar1;
                    }
                }
            }
#pragma unroll
            for (int g = 0; g < 4; g++) {          // CNOT ring
                const int cbit = 8 >> g;
                const int tbit = 8 >> ((g + 1) & 3);
#pragma unroll
                for (int i = 0; i < 16; i++) {
                    if ((i & cbit) && !(i & tbit)) {
                        int j = i | tbit;
                        float tr = vr[i]; vr[i] = vr[j]; vr[j] = tr;
                        float ti = vi[i]; vi[i] = vi[j]; vi[j] = ti;
                    }
                }
            }
        }
#pragma unroll
        for (int r = 0; r < 16; r++) {
            sUr[col][r] = vr[r];
            sUi[col][r] = vi[r];
        }
    }
    __syncthreads();

    for (int e = tid; e < 4 * 256; e += blockDim.x) {
        int i = e >> 8;
        int j = (e >> 4) & 15;
        int k = e & 15;
        int zmask = 8 >> i;
        float acc = 0.f;
#pragma unroll
        for (int r = 0; r < 16; r++) {
            float t = sUr[j][r] * sUr[k][r] + sUi[j][r] * sUi[k][r];
            acc += (r & zmask) ? -t : t;
        }
        sM[i][j][k] = acc;
    }
    __syncthreads();

    for (int m = tid; m < 81; m += blockDim.x) {
        int p = m / 9, q = m % 9;
        int mq[4] = { p / 3, p % 3, q / 3, q % 3 };
        float c0 = 0.f, c1 = 0.f, c2 = 0.f, c3 = 0.f;
        for (int t = 0; t < 16; t++) {
            int j = 0, k = 0;
            float sgn = 1.f;
#pragma unroll
            for (int qq = 0; qq < 4; qq++) {
                int b = (t >> (3 - qq)) & 1;
                int jq, kq;
                if (mq[qq] == 0)      { jq = b; kq = b; }
                else if (mq[qq] == 1) { jq = b; kq = b; if (b) sgn = -sgn; }
                else                  { jq = b; kq = 1 - b; }
                j = (j << 1) | jq;
                k = (k << 1) | kq;
            }
            c0 += sgn * sM[0][j][k];
            c1 += sgn * sM[1][j][k];
            c2 += sgn * sM[2][j][k];
            c3 += sgn * sM[3][j][k];
        }
        g_C[h * 81 + m] = make_float4(c0 * 0.0625f, c1 * 0.0625f,
                                      c2 * 0.0625f, c3 * 0.0625f);
    }
}

// ---------------------------------------------------------------------------
// Main: block = 128 threads, 256 tokens.
// Phase 1: T=2 tokens/thread, C from __constant__ (zero l1tex traffic),
//          ev -> smem tile [256][33] (conflict-free).
// Phase 2: block GEMM out = ev @ Wt + b, thread = 8 tokens x 8 outputs.
// ---------------------------------------------------------------------------
__global__ __launch_bounds__(128, 4) void qmha_main(
    const float* __restrict__ x,
    const float* __restrict__ W,      // [32][32] row-major
    const float* __restrict__ bvec,   // [32]
    float* __restrict__ out,
    int ntok)
{
    __shared__ float sEv[256 * 33];
    __shared__ __align__(16) float sWt[32 * 32];  // sWt[k*32+j] = W[j*32+k]
    __shared__ float sb[32];

    int tid = threadIdx.x;
    for (int i = tid; i < 1024; i += 128) {
        int k = i >> 5, j = i & 31;
        sWt[k * 32 + j] = W[j * 32 + k];
    }
    if (tid < 32) sb[tid] = bvec[tid];

    int base = blockIdx.x * 256;
    int tA = base + tid;
    int tB = tA + 128;
    const float4* xA4 = reinterpret_cast<const float4*>(
        x + (size_t)(tA < ntok ? tA : 0) * 32);
    const float4* xB4 = reinterpret_cast<const float4*>(
        x + (size_t)(tB < ntok ? tB : 0) * 32);

    // ---- Phase 1 ----
#pragma unroll
    for (int h = 0; h < NH; h++) {
        float4 aA = xA4[h];
        float4 aB = xB4[h];
        float cA0, sA0, cA1, sA1, cA2, sA2, cA3, sA3;
        float cB0, sB0, cB1, sB1, cB2, sB2, cB3, sB3;
        __sincosf(aA.x, &sA0, &cA0);
        __sincosf(aA.y, &sA1, &cA1);
        __sincosf(aA.z, &sA2, &cA2);
        __sincosf(aA.w, &sA3, &cA3);
        __sincosf(aB.x, &sB0, &cB0);
        __sincosf(aB.y, &sB1, &cB1);
        __sincosf(aB.z, &sB2, &cB2);
        __sincosf(aB.w, &sB3, &cB3);

        float g01A[9] = { 1.f, cA1, sA1, cA0, cA0*cA1, cA0*sA1, sA0, sA0*cA1, sA0*sA1 };
        float g01B[9] = { 1.f, cB1, sB1, cB0, cB0*cB1, cB0*sB1, sB0, sB0*cB1, sB0*sB1 };
        unsigned long long gA23d[9], gB23d[9];
        {
            float gA23[9] = { 1.f, cA3, sA3, cA2, cA2*cA3, cA2*sA3, sA2, sA2*cA3, sA2*sA3 };
            float gB23[9] = { 1.f, cB3, sB3, cB2, cB2*cB3, cB2*sB3, sB2, sB2*cB3, sB2*sB3 };
#pragma unroll
            for (int q = 0; q < 9; q++) {
                gA23d[q] = pk2(gA23[q], gA23[q]);
                gB23d[q] = pk2(gB23[q], gB23[q]);
            }
        }

        unsigned long long evA01 = 0ULL, evA23 = 0ULL;
        unsigned long long evB01 = 0ULL, evB23 = 0ULL;
#pragma unroll
        for (int p = 0; p < 9; p++) {
            unsigned long long tA01 = 0ULL, tA23 = 0ULL;
            unsigned long long tB01 = 0ULL, tB23 = 0ULL;
#pragma unroll
            for (int q = 0; q < 9; q++) {
                ulonglong2 cc = c_C[h * 81 + p * 9 + q];   // LDC, warp-uniform
                fma2(tA01, cc.x, gA23d[q]);
                fma2(tA23, cc.y, gA23d[q]);
                fma2(tB01, cc.x, gB23d[q]);
                fma2(tB23, cc.y, gB23d[q]);
            }
            unsigned long long gpA = pk2(g01A[p], g01A[p]);
            unsigned long long gpB = pk2(g01B[p], g01B[p]);
            fma2(evA01, gpA, tA01);
            fma2(evA23, gpA, tA23);
            fma2(evB01, gpB, tB01);
            fma2(evB23, gpB, tB23);
        }

        float e0, e1, e2, e3;
        unpk2(e0, e1, evA01); unpk2(e2, e3, evA23);
        sEv[tid * 33 + h * 4 + 0] = e0;
        sEv[tid * 33 + h * 4 + 1] = e1;
        sEv[tid * 33 + h * 4 + 2] = e2;
        sEv[tid * 33 + h * 4 + 3] = e3;
        unpk2(e0, e1, evB01); unpk2(e2, e3, evB23);
        sEv[(tid + 128) * 33 + h * 4 + 0] = e0;
        sEv[(tid + 128) * 33 + h * 4 + 1] = e1;
        sEv[(tid + 128) * 33 + h * 4 + 2] = e2;
        sEv[(tid + 128) * 33 + h * 4 + 3] = e3;
    }

    __syncthreads();

    // ---- Phase 2: out[256][32] = ev[256][32] @ sWt[32][32] + b ----
    int lane = tid & 31;     // token group (strided by 32)
    int jg = tid >> 5;       // output group of 8

    unsigned long long acc[8][4];
#pragma unroll
    for (int m = 0; m < 8; m++)
#pragma unroll
        for (int c = 0; c < 4; c++)
            acc[m][c] = pk2(sb[jg * 8 + 2 * c], sb[jg * 8 + 2 * c + 1]);

#pragma unroll
    for (int k = 0; k < 32; k++) {
        const ulonglong2* w2 =
            reinterpret_cast<const ulonglong2*>(sWt + k * 32 + jg * 8);
        ulonglong2 wa = w2[0];   // outputs jg*8+0..3
        ulonglong2 wb = w2[1];   // outputs jg*8+4..7
#pragma unroll
        for (int m = 0; m < 8; m++) {
            float e = sEv[(lane + 32 * m) * 33 + k];
            unsigned long long ed = pk2(e, e);
            fma2(acc[m][0], ed, wa.x);
            fma2(acc[m][1], ed, wa.y);
            fma2(acc[m][2], ed, wb.x);
            fma2(acc[m][3], ed, wb.y);
        }
    }

#pragma unroll
    for (int m = 0; m < 8; m++) {
        int t = base + lane + 32 * m;
        if (t < ntok) {
            float4* o = reinterpret_cast<float4*>(out + (size_t)t * 32 + jg * 8);
            float a0, a1, a2, a3;
            unpk2(a0, a1, acc[m][0]);
            unpk2(a2, a3, acc[m][1]);
            o[0] = make_float4(a0, a1, a2, a3);
            unpk2(a0, a1, acc[m][2]);
            unpk2(a2, a3, acc[m][3]);
            o[1] = make_float4(a0, a1, a2, a3);
        }
    }
}

extern "C" void kernel_launch(void* const* d_in, const int* in_sizes, int n_in,
                              void* d_out, int out_size) {
    const float* x      = (const float*)d_in[0];  // [B,S,32]
    const float* params = (const float*)d_in[1];  // [8,2,4,3]
    const float* W      = (const float*)d_in[2];  // [32,32]
    const float* b      = (const float*)d_in[3];  // [32]
    float* out = (float*)d_out;

    int ntok = in_sizes[0] / 32;

    build_all<<<NH, 128>>>(params);

    // Plain D2D memcpy into the constant bank (vanilla memcpy node under
    // graph capture; symbol addresses resolved via host-side queries).
    void* gC_ptr = nullptr;
    void* cC_ptr = nullptr;
    cudaGetSymbolAddress(&gC_ptr, g_C);
    cudaGetSymbolAddress(&cC_ptr, c_C);
    cudaMemcpyAsync(cC_ptr, gC_ptr, sizeof(float4) * NH * 81,
                    cudaMemcpyDeviceToDevice, 0);

    int blocks = (ntok + 255) / 256;
    qmha_main<<<blocks, 128>>>(x, W, b, out, ntok);
}